// round 1
// baseline (speedup 1.0000x reference)
#include <cuda_runtime.h>
#include <cstdint>

#define B_  2
#define L_  8192
#define D_  1024
#define H_  16
#define NF  16384
#define PI2F 6.28318530717958647692f

// ---------------- scratch (device globals; no allocations allowed) ----------------
__device__ float  g_u[B_ * D_ * L_];   // layernorm output, transposed [b][c][t]
__device__ float  g_y[B_ * D_ * L_];   // conv output,      transposed [b][c][t]
__device__ float2 g_Kf[H_ * NF];       // filter spectrum, DIF-scrambled order, scaled 1/NF

// TW[m] = exp(-2*pi*i*m/32), m = 0..15 (forward kernel; conjugate for inverse)
__constant__ float2 c_tw[16] = {
    { 1.000000000000000f,  0.000000000000000f},
    { 0.980785280403230f, -0.195090322016128f},
    { 0.923879532511287f, -0.382683432365090f},
    { 0.831469612302545f, -0.555570233019602f},
    { 0.707106781186548f, -0.707106781186548f},
    { 0.555570233019602f, -0.831469612302545f},
    { 0.382683432365090f, -0.923879532511287f},
    { 0.195090322016128f, -0.980785280403230f},
    { 0.000000000000000f, -1.000000000000000f},
    {-0.195090322016128f, -0.980785280403230f},
    {-0.382683432365090f, -0.923879532511287f},
    {-0.555570233019602f, -0.831469612302545f},
    {-0.707106781186548f, -0.707106781186548f},
    {-0.831469612302545f, -0.555570233019602f},
    {-0.923879532511287f, -0.382683432365090f},
    {-0.980785280403230f, -0.195090322016128f},
};

__device__ __forceinline__ float2 cmul(float2 a, float2 b) {
    return make_float2(fmaf(a.x, b.x, -a.y * b.y), fmaf(a.x, b.y, a.y * b.x));
}
__device__ __forceinline__ float2 eix(float ang) {   // e^{+i*ang}
    float s, c;
    __sincosf(ang, &s, &c);
    return make_float2(c, s);
}
// smem address swizzle (bijection): makes every stage's access pattern
// conflict-free with purely STATIC register indices.
__device__ __forceinline__ int sw(int a) { return a ^ ((a >> 5) & 31); }

// ---------------- in-register DFT (natural in, natural out) ----------------
template <int NR, int BS, bool INV>
__device__ __forceinline__ void dft_layer(float2* r) {
    constexpr int half = BS / 2;
#pragma unroll
    for (int base = 0; base < NR; base += BS) {
#pragma unroll
        for (int j = 0; j < half; j++) {
            float2 a = r[base + j], b = r[base + j + half];
            float2 s = make_float2(a.x + b.x, a.y + b.y);
            float2 d = make_float2(a.x - b.x, a.y - b.y);
            constexpr int mstep = 32 / BS;
            float2 w = c_tw[j * mstep];
            if (INV) w.y = -w.y;
            r[base + j]        = s;
            r[base + j + half] = cmul(d, w);
        }
    }
}
#define SWAP2(r, i, j) { float2 t_ = r[i]; r[i] = r[j]; r[j] = t_; }

template <bool INV>
__device__ __forceinline__ void dft16(float2* r) {
    dft_layer<16, 16, INV>(r);
    dft_layer<16, 8,  INV>(r);
    dft_layer<16, 4,  INV>(r);
    dft_layer<16, 2,  INV>(r);
    // 4-bit bit-reversal -> natural order
    SWAP2(r, 1, 8)  SWAP2(r, 2, 4)  SWAP2(r, 3, 12)
    SWAP2(r, 5, 10) SWAP2(r, 7, 14) SWAP2(r, 11, 13)
}
template <bool INV>
__device__ __forceinline__ void dft32(float2* r) {
    dft_layer<32, 32, INV>(r);
    dft_layer<32, 16, INV>(r);
    dft_layer<32, 8,  INV>(r);
    dft_layer<32, 4,  INV>(r);
    dft_layer<32, 2,  INV>(r);
    // 5-bit bit-reversal -> natural order
    SWAP2(r, 1, 16)  SWAP2(r, 2, 8)   SWAP2(r, 3, 24)  SWAP2(r, 5, 20)
    SWAP2(r, 6, 12)  SWAP2(r, 7, 28)  SWAP2(r, 9, 18)  SWAP2(r, 11, 26)
    SWAP2(r, 13, 22) SWAP2(r, 15, 30) SWAP2(r, 19, 25) SWAP2(r, 23, 29)
}

// ================= Kernel 1: LayerNorm + transpose (x -> g_u[b][c][t]) =================
__global__ __launch_bounds__(1024) void k_ln_transpose(
    const float* __restrict__ x,
    const float* __restrict__ gamma,
    const float* __restrict__ beta)
{
    extern __shared__ float tile[];             // 32 x 1025 floats
    __shared__ float s_mu[32], s_rs[32];
    const int b   = blockIdx.y;
    const int t0  = blockIdx.x << 5;
    const int tid = threadIdx.x;
    const float* xp = x + (size_t)(b * L_ + t0) * D_;

#pragma unroll
    for (int i = 0; i < 32; i++)                // row i, col tid (coalesced)
        tile[i * 1025 + tid] = xp[i * 1024 + tid];
    __syncthreads();

    const int w = tid >> 5, lane = tid & 31;    // warp w reduces row w
    {
        float s = 0.f, s2 = 0.f;
        const float* rowp = tile + w * 1025;
#pragma unroll
        for (int m = 0; m < 32; m++) {
            float v = rowp[lane + (m << 5)];
            s += v;
            s2 = fmaf(v, v, s2);
        }
#pragma unroll
        for (int o = 16; o; o >>= 1) {
            s  += __shfl_xor_sync(0xffffffffu, s, o);
            s2 += __shfl_xor_sync(0xffffffffu, s2, o);
        }
        if (lane == 0) {
            float mu  = s * (1.f / 1024.f);
            float var = s2 * (1.f / 1024.f) - mu * mu;
            s_mu[w] = mu;
            s_rs[w] = rsqrtf(var + 1e-5f);
        }
    }
    __syncthreads();

#pragma unroll
    for (int i = 0; i < 32; i++) {
        int idx = (i << 10) + tid;
        int c = idx >> 5, r = idx & 31;         // warp: fixed c, r=0..31 -> coalesced store
        float v = (tile[r * 1025 + c] - s_mu[r]) * s_rs[r] * gamma[c] + beta[c];
        g_u[(b * D_ + c) * L_ + t0 + r] = v;
    }
}

// ================= Kernel 2: filter spectrum (DIF-scrambled, scaled 1/NF) =================
__global__ __launch_bounds__(512) void k_filter_fft(const float* __restrict__ wgt)
{
    extern __shared__ float2 sm[];              // 16384 complex
    const int head = blockIdx.x;
    const int tid  = threadIdx.x;

    // ---- fwd stage 1: L=16384, R=16, s=1024 (global -> smem)
#pragma unroll
    for (int rep = 0; rep < 2; rep++) {
        int j = tid + (rep << 9);
        float2 r[16];
#pragma unroll
        for (int k = 0; k < 16; k++) {
            int t = j + (k << 10);
            r[k] = make_float2(t < L_ ? wgt[t * H_ + head] : 0.f, 0.f);
        }
        dft16<false>(r);
        float2 w1 = eix(-(PI2F / 16384.f) * (float)j);
        float2 wk = make_float2(1.f, 0.f);
#pragma unroll
        for (int k = 0; k < 16; k++) {
            sm[sw(j + (k << 10))] = cmul(r[k], wk);
            wk = cmul(wk, w1);
        }
    }
    __syncthreads();
    // ---- fwd stage 2: L=1024, R=32, s=32
    {
        int blk = tid >> 5, j = tid & 31;
        int base = (blk << 10) + j;
        float2 r[32];
#pragma unroll
        for (int k = 0; k < 32; k++) r[k] = sm[sw(base + (k << 5))];
        dft32<false>(r);
        float2 w1 = eix(-(PI2F / 1024.f) * (float)j);
        float2 wk = make_float2(1.f, 0.f);
#pragma unroll
        for (int k = 0; k < 32; k++) {
            sm[sw(base + (k << 5))] = cmul(r[k], wk);
            wk = cmul(wk, w1);
        }
    }
    __syncthreads();
    // ---- fwd stage 3: blocks of 32, plain DFT32, scale, store to global
    {
        int base = tid << 5;
        float2 r[32];
#pragma unroll
        for (int k = 0; k < 32; k++) r[k] = sm[sw(base + k)];
        dft32<false>(r);
        const float sc = 1.f / (float)NF;
        float2* out = g_Kf + head * NF + base;
#pragma unroll
        for (int k = 0; k < 32; k++)
            out[k] = make_float2(r[k].x * sc, r[k].y * sc);
    }
}

// ================= Kernel 3: packed-complex FFT conv (2 channels / CTA) =================
__global__ __launch_bounds__(512) void k_conv()
{
    extern __shared__ float2 sm[];              // 16384 complex = 128 KB
    const int tid  = threadIdx.x;
    const int bc   = blockIdx.x;                // 0..1023
    const int b    = bc >> 9;
    const int pair = bc & 511;
    const int c0   = pair << 1;
    const int head = c0 >> 6;
    const float* __restrict__ u0 = g_u + (b * D_ + c0) * L_;
    const float* __restrict__ u1 = u0 + L_;

    // ---- fwd stage 1 (global -> smem): z = u0 + i*u1, zero-padded to 16384
#pragma unroll
    for (int rep = 0; rep < 2; rep++) {
        int j = tid + (rep << 9);
        float2 r[16];
#pragma unroll
        for (int k = 0; k < 16; k++) {
            int t = j + (k << 10);
            r[k] = (t < L_) ? make_float2(u0[t], u1[t]) : make_float2(0.f, 0.f);
        }
        dft16<false>(r);
        float2 w1 = eix(-(PI2F / 16384.f) * (float)j);
        float2 wk = make_float2(1.f, 0.f);
#pragma unroll
        for (int k = 0; k < 16; k++) {
            sm[sw(j + (k << 10))] = cmul(r[k], wk);
            wk = cmul(wk, w1);
        }
    }
    __syncthreads();
    // ---- fwd stage 2
    {
        int blk = tid >> 5, j = tid & 31;
        int base = (blk << 10) + j;
        float2 r[32];
#pragma unroll
        for (int k = 0; k < 32; k++) r[k] = sm[sw(base + (k << 5))];
        dft32<false>(r);
        float2 w1 = eix(-(PI2F / 1024.f) * (float)j);
        float2 wk = make_float2(1.f, 0.f);
#pragma unroll
        for (int k = 0; k < 32; k++) {
            sm[sw(base + (k << 5))] = cmul(r[k], wk);
            wk = cmul(wk, w1);
        }
    }
    __syncthreads();
    // ---- fused: fwd DFT32 -> pointwise * Kf (same scrambled order) -> inv DFT32
    {
        int base = tid << 5;
        const float2* __restrict__ Kf = g_Kf + head * NF + base;
        float2 r[32];
#pragma unroll
        for (int k = 0; k < 32; k++) r[k] = sm[sw(base + k)];
        dft32<false>(r);
#pragma unroll
        for (int k = 0; k < 32; k++) r[k] = cmul(r[k], Kf[k]);
        dft32<true>(r);
#pragma unroll
        for (int k = 0; k < 32; k++) sm[sw(base + k)] = r[k];
    }
    __syncthreads();
    // ---- inverse stage 2 (pre-twiddle conj, then inverse DFT32)
    {
        int blk = tid >> 5, j = tid & 31;
        int base = (blk << 10) + j;
        float2 r[32];
        float2 w1 = eix((PI2F / 1024.f) * (float)j);
        float2 wk = make_float2(1.f, 0.f);
#pragma unroll
        for (int k = 0; k < 32; k++) {
            r[k] = cmul(sm[sw(base + (k << 5))], wk);
            wk = cmul(wk, w1);
        }
        dft32<true>(r);
#pragma unroll
        for (int k = 0; k < 32; k++) sm[sw(base + (k << 5))] = r[k];
    }
    __syncthreads();
    // ---- inverse stage 1 (smem -> global); only first L_ outputs needed (k < 8)
    float* __restrict__ y0 = g_y + (b * D_ + c0) * L_;
    float* __restrict__ y1 = y0 + L_;
#pragma unroll
    for (int rep = 0; rep < 2; rep++) {
        int j = tid + (rep << 9);
        float2 r[16];
        float2 w1 = eix((PI2F / 16384.f) * (float)j);
        float2 wk = make_float2(1.f, 0.f);
#pragma unroll
        for (int k = 0; k < 16; k++) {
            r[k] = cmul(sm[sw(j + (k << 10))], wk);
            wk = cmul(wk, w1);
        }
        dft16<true>(r);
#pragma unroll
        for (int k = 0; k < 8; k++) {
            int t = j + (k << 10);
            y0[t] = r[k].x;     // conv(u[c0], K)
            y1[t] = r[k].y;     // conv(u[c1], K)
        }
    }
}

// ================= Kernel 4: out[b][t][c] = y + u*param_D (transpose back) =================
__global__ __launch_bounds__(256) void k_combine(
    const float* __restrict__ pD, float* __restrict__ out)
{
    __shared__ float ys[32 * 129];
    __shared__ float us[32 * 129];
    const int b   = blockIdx.z;
    const int c0  = blockIdx.y << 5;            // 32-channel tile
    const int t0  = blockIdx.x << 7;            // 128-t tile
    const int tid = threadIdx.x;

#pragma unroll
    for (int i = 0; i < 16; i++) {
        int idx = (i << 8) + tid;
        int cc = idx >> 7, tt = idx & 127;      // coalesced loads along t
        int gi = (b * D_ + c0 + cc) * L_ + t0 + tt;
        ys[cc * 129 + tt] = g_y[gi];
        us[cc * 129 + tt] = g_u[gi];
    }
    __syncthreads();
#pragma unroll
    for (int i = 0; i < 16; i++) {
        int idx = (i << 8) + tid;
        int tt = idx >> 5, cc = idx & 31;       // coalesced stores along c
        float v = ys[cc * 129 + tt] + us[cc * 129 + tt] * pD[c0 + cc];
        out[(size_t)(b * L_ + t0 + tt) * D_ + c0 + cc] = v;
    }
}

// =========================================================================
extern "C" void kernel_launch(void* const* d_in, const int* in_sizes, int n_in,
                              void* d_out, int out_size)
{
    (void)in_sizes; (void)n_in; (void)out_size;
    const float* x     = (const float*)d_in[0];   // (2, 8192, 1024) f32
    const float* wgt   = (const float*)d_in[1];   // (8192, 16)      f32
    const float* pD    = (const float*)d_in[2];   // (1024,)         f32
    const float* gamma = (const float*)d_in[3];   // (1024,)         f32
    const float* beta  = (const float*)d_in[4];   // (1024,)         f32
    float* out = (float*)d_out;                   // (2, 8192, 1024) f32

    cudaFuncSetAttribute(k_ln_transpose, cudaFuncAttributeMaxDynamicSharedMemorySize, 32 * 1025 * 4);
    cudaFuncSetAttribute(k_filter_fft,   cudaFuncAttributeMaxDynamicSharedMemorySize, NF * 8);
    cudaFuncSetAttribute(k_conv,         cudaFuncAttributeMaxDynamicSharedMemorySize, NF * 8);

    dim3 g1(L_ / 32, B_);
    k_ln_transpose<<<g1, 1024, 32 * 1025 * 4>>>(x, gamma, beta);
    k_filter_fft<<<H_, 512, NF * 8>>>(wgt);
    k_conv<<<B_ * D_ / 2, 512, NF * 8>>>();
    dim3 g4(L_ / 128, D_ / 32, B_);
    k_combine<<<g4, 256>>>(pD, out);
}